// round 8
// baseline (speedup 1.0000x reference)
#include <cuda_runtime.h>
#include <cstdint>

#define Bz 8
#define Sq 1024
#define Ed 768
#define Hh 12
#define Dd 64
#define N3 2304
#define TOPK 409
#define QT 16
#define KTT 128
#define KVP 68     // K/V smem row stride (words)
#define QSP 68     // q smem row stride
#define SCP 1028   // scores row stride (4*gid mod 32 distinct -> conflict-free frags)

#define ASTR 20    // gemm A smem row stride
#define BSTR 136   // gemm B smem row stride

// ---- scratch (allocation-free rule: __device__ globals) ----
__device__ float g_Q[Bz*Hh*Sq*Dd];
__device__ float g_K[Bz*Hh*Sq*Dd];
__device__ float g_V[Bz*Hh*Sq*Dd];
__device__ float g_AO[Bz*Sq*Ed];     // [b,s,h,d] = [8192, 768]

// ---- cp.async helpers ----
__device__ __forceinline__ void cp16(void* smem_dst, const void* gmem_src) {
    unsigned s = (unsigned)__cvta_generic_to_shared(smem_dst);
    asm volatile("cp.async.cg.shared.global [%0], [%1], 16;" :: "r"(s), "l"(gmem_src));
}
__device__ __forceinline__ void cp_commit() { asm volatile("cp.async.commit_group;"); }
template<int N>
__device__ __forceinline__ void cp_wait() { asm volatile("cp.async.wait_group %0;" :: "n"(N)); }

// ---- 3xTF32 helpers ----
__device__ __forceinline__ void split_tf32(float x, uint32_t& hi, uint32_t& lo) {
    uint32_t h;
    asm("cvt.rna.tf32.f32 %0, %1;" : "=r"(h) : "f"(x));
    float l = x - __uint_as_float(h);
    uint32_t lw;
    asm("cvt.rna.tf32.f32 %0, %1;" : "=r"(lw) : "f"(l));
    hi = h; lo = lw;
}
__device__ __forceinline__ void mma_tf32(float4& d, const uint32_t a[4], const uint32_t b[2]) {
    asm volatile("mma.sync.aligned.m16n8k8.row.col.f32.tf32.tf32.f32 "
                 "{%0,%1,%2,%3}, {%4,%5,%6,%7}, {%8,%9}, {%0,%1,%2,%3};"
                 : "+f"(d.x), "+f"(d.y), "+f"(d.z), "+f"(d.w)
                 : "r"(a[0]), "r"(a[1]), "r"(a[2]), "r"(a[3]), "r"(b[0]), "r"(b[1]));
}

// ============================================================
// 3xTF32 GEMM (unchanged from R7, passing)
// ============================================================
template<int NDIM, bool SCATTER>
__global__ __launch_bounds__(256, 2) void gemm_tf32(const float* __restrict__ A_in,
                                                    const float* __restrict__ W,
                                                    const float* __restrict__ bias,
                                                    float* __restrict__ out) {
    const float* A = SCATTER ? A_in : (const float*)g_AO;   // device-side symbol!

    __shared__ float As[2][128*ASTR];
    __shared__ float Bs[2][16*BSTR];

    const int t    = threadIdx.x;
    const int warp = t >> 5, lane = t & 31;
    const int gid  = lane >> 2, tig = lane & 3;
    const int m0   = blockIdx.y * 128, n0 = blockIdx.x * 128;
    const int wm   = (warp >> 2) * 64;
    const int wn   = (warp & 3) * 32;

    auto issue = [&](int buf, int kt) {
        #pragma unroll
        for (int i = 0; i < 2; i++) {
            int f = t + 256*i;
            int m = f >> 2, kc = (f & 3) << 2;
            cp16(&As[buf][m*ASTR + kc], &A[(size_t)(m0 + m)*Ed + kt*16 + kc]);
        }
        #pragma unroll
        for (int i = 0; i < 2; i++) {
            int f = t + 256*i;
            int kr = f >> 5, nc = (f & 31) << 2;
            cp16(&Bs[buf][kr*BSTR + nc], &W[(size_t)(kt*16 + kr)*NDIM + n0 + nc]);
        }
        cp_commit();
    };

    float4 acc[4][4];
    #pragma unroll
    for (int i = 0; i < 4; i++)
        #pragma unroll
        for (int j = 0; j < 4; j++) acc[i][j] = make_float4(0.f, 0.f, 0.f, 0.f);

    issue(0, 0);
    const int NT = Ed / 16;
    for (int kt = 0; kt < NT; kt++) {
        if (kt + 1 < NT) { issue((kt + 1) & 1, kt + 1); cp_wait<1>(); }
        else             { cp_wait<0>(); }
        __syncthreads();
        const float* as = As[kt & 1];
        const float* bs = Bs[kt & 1];
        #pragma unroll
        for (int ko = 0; ko < 16; ko += 8) {
            uint32_t Bhi[4][2], Blo[4][2];
            #pragma unroll
            for (int j = 0; j < 4; j++) {
                const int nc = wn + 8*j + gid;
                split_tf32(bs[(ko + tig    )*BSTR + nc], Bhi[j][0], Blo[j][0]);
                split_tf32(bs[(ko + tig + 4)*BSTR + nc], Bhi[j][1], Blo[j][1]);
            }
            #pragma unroll
            for (int i = 0; i < 4; i++) {
                const int r0 = wm + 16*i + gid;
                uint32_t Ahi[4], Alo[4];
                split_tf32(as[ r0     *ASTR + ko + tig    ], Ahi[0], Alo[0]);
                split_tf32(as[(r0 + 8)*ASTR + ko + tig    ], Ahi[1], Alo[1]);
                split_tf32(as[ r0     *ASTR + ko + tig + 4], Ahi[2], Alo[2]);
                split_tf32(as[(r0 + 8)*ASTR + ko + tig + 4], Ahi[3], Alo[3]);
                #pragma unroll
                for (int j = 0; j < 4; j++) {
                    mma_tf32(acc[i][j], Alo, Bhi[j]);
                    mma_tf32(acc[i][j], Ahi, Blo[j]);
                    mma_tf32(acc[i][j], Ahi, Bhi[j]);
                }
            }
        }
        __syncthreads();
    }

    #pragma unroll
    for (int i = 0; i < 4; i++) {
        const int ma = m0 + wm + 16*i + gid;
        const int mb = ma + 8;
        #pragma unroll
        for (int j = 0; j < 4; j++) {
            const int nb = n0 + wn + 8*j + 2*tig;
            const float2 bv = *(const float2*)&bias[nb];
            float2 va = make_float2(acc[i][j].x + bv.x, acc[i][j].y + bv.y);
            float2 vb = make_float2(acc[i][j].z + bv.x, acc[i][j].w + bv.y);
            if (SCATTER) {
                const int which = nb / Ed;
                const int hh    = (nb % Ed) >> 6;
                const int d0    = nb & 63;
                float* dst = (which == 0) ? g_Q : (which == 1) ? g_K : g_V;
                {
                    int bb = ma >> 10, ss = ma & 1023;
                    *(float2*)&dst[(size_t)((bb*Hh + hh)*Sq + ss)*Dd + d0] = va;
                }
                {
                    int bb = mb >> 10, ss = mb & 1023;
                    *(float2*)&dst[(size_t)((bb*Hh + hh)*Sq + ss)*Dd + d0] = vb;
                }
            } else {
                *(float2*)&out[(size_t)ma * NDIM + nb] = va;
                *(float2*)&out[(size_t)mb * NDIM + nb] = vb;
            }
        }
    }
}

// ============================================================
// Fused attention with tensor-core (3xTF32) QK^T and PV.
// One CTA per (b*h, 16 q-rows). 256 thr, 2 CTAs/SM.
// ============================================================
__global__ __launch_bounds__(256, 2) void attn_kernel() {
    extern __shared__ float sm[];
    float* q_s  = sm;                   // 16*68  = 1088
    float* sc   = sm + 1088;            // 16*1028 = 16448
    float* kv   = sc + 16448;           // 128*68 = 8704
    float* invs = kv + 8704;            // 16
    // total 26256 floats = 105024 B

    const int t    = threadIdx.x;
    const int warp = t >> 5, lane = t & 31;
    const int gid  = lane >> 2, tig = lane & 3;
    const int bh = blockIdx.y;
    const int q0 = blockIdx.x * QT;
    const float* Qg = g_Q + (size_t)bh*Sq*Dd;
    const float* Kg = g_K + (size_t)bh*Sq*Dd;
    const float* Vg = g_V + (size_t)bh*Sq*Dd;

    const int prow = t >> 4, pc4 = (t & 15) << 2;
    float4 pf[8];
    auto ldg_tile = [&](const float* src, int kt0) {
        #pragma unroll
        for (int i = 0; i < 8; i++)
            pf[i] = *(const float4*)&src[(size_t)(kt0*KTT + prow + 16*i)*Dd + pc4];
    };
    auto sts_tile = [&]() {
        #pragma unroll
        for (int i = 0; i < 8; i++)
            *(float4*)&kv[(prow + 16*i)*KVP + pc4] = pf[i];
    };
    auto cp_tile = [&](const float* src, int kt0) {
        #pragma unroll
        for (int i = 0; i < 8; i++)
            cp16(&kv[(prow + 16*i)*KVP + pc4], &src[(size_t)(kt0*KTT + prow + 16*i)*Dd + pc4]);
        cp_commit();
    };

    // stage q tile (pre-scaled by 0.125 — exact power of 2)
    {
        float4 v = *(const float4*)&Qg[(size_t)(q0 + prow)*Dd + pc4];
        v.x *= 0.125f; v.y *= 0.125f; v.z *= 0.125f; v.w *= 0.125f;
        *(float4*)&q_s[prow*QSP + pc4] = v;
    }

    // ================= scores (tensor core) =================
    cp_tile(Kg, 0);
    ldg_tile(Kg, 1);
    cp_wait<0>(); __syncthreads();

    for (int it = 0; it < 8; it++) {
        float4 c0 = make_float4(0.f,0.f,0.f,0.f);
        float4 c1 = make_float4(0.f,0.f,0.f,0.f);
        #pragma unroll
        for (int ks = 0; ks < 8; ks++) {
            uint32_t Ah[4], Al[4], Bh[2], Bl[2];
            split_tf32(q_s[ gid     *QSP + ks*8 + tig    ], Ah[0], Al[0]);
            split_tf32(q_s[(gid + 8)*QSP + ks*8 + tig    ], Ah[1], Al[1]);
            split_tf32(q_s[ gid     *QSP + ks*8 + tig + 4], Ah[2], Al[2]);
            split_tf32(q_s[(gid + 8)*QSP + ks*8 + tig + 4], Ah[3], Al[3]);
            // keys warp*16 .. +7
            split_tf32(kv[(warp*16     + gid)*KVP + ks*8 + tig    ], Bh[0], Bl[0]);
            split_tf32(kv[(warp*16     + gid)*KVP + ks*8 + tig + 4], Bh[1], Bl[1]);
            mma_tf32(c0, Al, Bh); mma_tf32(c0, Ah, Bl); mma_tf32(c0, Ah, Bh);
            // keys warp*16+8 .. +15
            split_tf32(kv[(warp*16 + 8 + gid)*KVP + ks*8 + tig    ], Bh[0], Bl[0]);
            split_tf32(kv[(warp*16 + 8 + gid)*KVP + ks*8 + tig + 4], Bh[1], Bl[1]);
            mma_tf32(c1, Al, Bh); mma_tf32(c1, Ah, Bl); mma_tf32(c1, Ah, Bh);
        }
        const int kb = it*KTT + warp*16 + 2*tig;
        *(float2*)&sc[ gid   *SCP + kb    ] = make_float2(c0.x, c0.y);
        *(float2*)&sc[(gid+8)*SCP + kb    ] = make_float2(c0.z, c0.w);
        *(float2*)&sc[ gid   *SCP + kb + 8] = make_float2(c1.x, c1.y);
        *(float2*)&sc[(gid+8)*SCP + kb + 8] = make_float2(c1.z, c1.w);
        __syncthreads();
        if (it < 7) {
            sts_tile();
            if (it < 6) ldg_tile(Kg, it+2);
            __syncthreads();
        }
    }
    __syncthreads();

    cp_tile(Vg, 0);   // V0 flies during top-k

    // ====== exact top-k threshold + softmax in place ======
    {
        const int lane5 = t & 31;
        for (int r = warp*2; r < warp*2 + 2; r++) {
            float* row = sc + r*SCP;
            unsigned u[32];
            float mx = -3.4e38f;
            #pragma unroll
            for (int i = 0; i < 32; i++) {
                float f = row[i*32 + lane5];
                mx = fmaxf(mx, f);
                unsigned b = __float_as_uint(f);
                u[i] = b ^ (unsigned)(((int)b >> 31) | (int)0x80000000);
            }
            #pragma unroll
            for (int o = 16; o; o >>= 1) mx = fmaxf(mx, __shfl_xor_sync(0xffffffffu, mx, o));

            unsigned pref = 0;
            #pragma unroll 1
            for (int bb = 31; bb >= 0; bb--) {
                unsigned trial = pref | (1u << bb);
                int c = 0;
                #pragma unroll
                for (int i = 0; i < 32; i++) c += (u[i] >= trial) ? 1 : 0;
                c = (int)__reduce_add_sync(0xffffffffu, (unsigned)c);
                if (c >= TOPK) pref = trial;
            }

            float ssum = 0.f;
            #pragma unroll
            for (int i = 0; i < 32; i++) {
                float p = 0.f;
                if (u[i] >= pref) {
                    unsigned b = (u[i] & 0x80000000u) ? (u[i] ^ 0x80000000u) : ~u[i];
                    p = __expf(__uint_as_float(b) - mx);
                }
                ssum += p;
                row[i*32 + lane5] = p;
            }
            #pragma unroll
            for (int o = 16; o; o >>= 1) ssum += __shfl_xor_sync(0xffffffffu, ssum, o);
            if (lane5 == 0) invs[r] = 1.f / ssum;
        }
    }

    ldg_tile(Vg, 1);
    cp_wait<0>(); __syncthreads();   // V0 ready, p + invs visible

    // ================= PV (tensor core) =================
    // warp owns d-cols [8*warp, 8*warp+8); one m16n8 acc across all tiles
    float4 oc = make_float4(0.f,0.f,0.f,0.f);
    for (int it = 0; it < 8; it++) {
        const int kb = it*KTT;
        #pragma unroll
        for (int ks = 0; ks < 16; ks++) {
            uint32_t Ah[4], Al[4], Bh[2], Bl[2];
            split_tf32(sc[ gid   *SCP + kb + ks*8 + tig    ], Ah[0], Al[0]);
            split_tf32(sc[(gid+8)*SCP + kb + ks*8 + tig    ], Ah[1], Al[1]);
            split_tf32(sc[ gid   *SCP + kb + ks*8 + tig + 4], Ah[2], Al[2]);
            split_tf32(sc[(gid+8)*SCP + kb + ks*8 + tig + 4], Ah[3], Al[3]);
            split_tf32(kv[(ks*8 + tig    )*KVP + warp*8 + gid], Bh[0], Bl[0]);
            split_tf32(kv[(ks*8 + tig + 4)*KVP + warp*8 + gid], Bh[1], Bl[1]);
            mma_tf32(oc, Al, Bh); mma_tf32(oc, Ah, Bl); mma_tf32(oc, Ah, Bh);
        }
        __syncthreads();
        if (it < 7) {
            sts_tile();
            if (it < 6) ldg_tile(Vg, it+2);
            __syncthreads();
        }
    }

    // epilogue: normalize and store
    {
        const int bb = bh / Hh, hh = bh % Hh;
        const float iv0 = invs[gid], iv1 = invs[gid + 8];
        const int d0 = warp*8 + 2*tig;
        float2 r0 = make_float2(oc.x * iv0, oc.y * iv0);
        float2 r1 = make_float2(oc.z * iv1, oc.w * iv1);
        *(float2*)&g_AO[(size_t)((bb*Sq + q0 + gid    )*Hh + hh)*Dd + d0] = r0;
        *(float2*)&g_AO[(size_t)((bb*Sq + q0 + gid + 8)*Hh + hh)*Dd + d0] = r1;
    }
}

// ============================================================
// launch
// ============================================================
extern "C" void kernel_launch(void* const* d_in, const int* in_sizes, int n_in,
                              void* d_out, int out_size) {
    const float* hidden = (const float*)d_in[0];
    const float* Wqkv   = (const float*)d_in[1];
    const float* bqkv   = (const float*)d_in[2];
    const float* Wproj  = (const float*)d_in[3];
    const float* bproj  = (const float*)d_in[4];
    float* out = (float*)d_out;

    const int attn_smem = (1088 + 16448 + 8704 + 16) * (int)sizeof(float); // 105024
    cudaFuncSetAttribute(attn_kernel, cudaFuncAttributeMaxDynamicSharedMemorySize, attn_smem);

    gemm_tf32<N3, true ><<<dim3(N3/128, (Bz*Sq)/128), 256>>>(hidden, Wqkv, bqkv, nullptr);
    attn_kernel<<<dim3(Sq/QT, Bz*Hh), 256, attn_smem>>>();
    gemm_tf32<Ed, false><<<dim3(Ed/128, (Bz*Sq)/128), 256>>>(nullptr, Wproj, bproj, out);
}

// round 9
// speedup vs baseline: 1.8184x; 1.8184x over previous
#include <cuda_runtime.h>
#include <cstdint>

#define Bz 8
#define Sq 1024
#define Ed 768
#define Hh 12
#define Dd 64
#define N3 2304
#define TOPK 409
#define QT 16
#define KTT 128
#define KVP 68     // K/V smem row stride (words)
#define QSP 68     // q smem row stride
#define SCP 1028   // scores row stride

#define ASTR 20
#define BSTR 136

// ---- scratch (allocation-free rule: __device__ globals) ----
__device__ float g_Q[Bz*Hh*Sq*Dd];
__device__ float g_K[Bz*Hh*Sq*Dd];
__device__ float g_V[Bz*Hh*Sq*Dd];
__device__ float g_AO[Bz*Sq*Ed];     // [b,s,h,d] = [8192, 768]

// ---- cp.async helpers ----
__device__ __forceinline__ void cp16(void* smem_dst, const void* gmem_src) {
    unsigned s = (unsigned)__cvta_generic_to_shared(smem_dst);
    asm volatile("cp.async.cg.shared.global [%0], [%1], 16;" :: "r"(s), "l"(gmem_src));
}
__device__ __forceinline__ void cp_commit() { asm volatile("cp.async.commit_group;"); }
template<int N>
__device__ __forceinline__ void cp_wait() { asm volatile("cp.async.wait_group %0;" :: "n"(N)); }

// ---- tf32 helpers ----
__device__ __forceinline__ uint32_t f2tf(float x) {
    uint32_t r; asm("cvt.rna.tf32.f32 %0, %1;" : "=r"(r) : "f"(x)); return r;
}
__device__ __forceinline__ void split_tf32(float x, uint32_t& hi, uint32_t& lo) {
    uint32_t h;
    asm("cvt.rna.tf32.f32 %0, %1;" : "=r"(h) : "f"(x));
    float l = x - __uint_as_float(h);
    uint32_t lw;
    asm("cvt.rna.tf32.f32 %0, %1;" : "=r"(lw) : "f"(l));
    hi = h; lo = lw;
}
__device__ __forceinline__ void mma_tf32(float4& d, const uint32_t a[4], const uint32_t b[2]) {
    asm volatile("mma.sync.aligned.m16n8k8.row.col.f32.tf32.tf32.f32 "
                 "{%0,%1,%2,%3}, {%4,%5,%6,%7}, {%8,%9}, {%0,%1,%2,%3};"
                 : "+f"(d.x), "+f"(d.y), "+f"(d.z), "+f"(d.w)
                 : "r"(a[0]), "r"(a[1]), "r"(a[2]), "r"(a[3]), "r"(b[0]), "r"(b[1]));
}

// ============================================================
// 3xTF32 GEMM (unchanged from R7, passing at 476us)
// ============================================================
template<int NDIM, bool SCATTER>
__global__ __launch_bounds__(256, 2) void gemm_tf32(const float* __restrict__ A_in,
                                                    const float* __restrict__ W,
                                                    const float* __restrict__ bias,
                                                    float* __restrict__ out) {
    const float* A = SCATTER ? A_in : (const float*)g_AO;   // device-side symbol!

    __shared__ float As[2][128*ASTR];
    __shared__ float Bs[2][16*BSTR];

    const int t    = threadIdx.x;
    const int warp = t >> 5, lane = t & 31;
    const int gid  = lane >> 2, tig = lane & 3;
    const int m0   = blockIdx.y * 128, n0 = blockIdx.x * 128;
    const int wm   = (warp >> 2) * 64;
    const int wn   = (warp & 3) * 32;

    auto issue = [&](int buf, int kt) {
        #pragma unroll
        for (int i = 0; i < 2; i++) {
            int f = t + 256*i;
            int m = f >> 2, kc = (f & 3) << 2;
            cp16(&As[buf][m*ASTR + kc], &A[(size_t)(m0 + m)*Ed + kt*16 + kc]);
        }
        #pragma unroll
        for (int i = 0; i < 2; i++) {
            int f = t + 256*i;
            int kr = f >> 5, nc = (f & 31) << 2;
            cp16(&Bs[buf][kr*BSTR + nc], &W[(size_t)(kt*16 + kr)*NDIM + n0 + nc]);
        }
        cp_commit();
    };

    float4 acc[4][4];
    #pragma unroll
    for (int i = 0; i < 4; i++)
        #pragma unroll
        for (int j = 0; j < 4; j++) acc[i][j] = make_float4(0.f, 0.f, 0.f, 0.f);

    issue(0, 0);
    const int NT = Ed / 16;
    for (int kt = 0; kt < NT; kt++) {
        if (kt + 1 < NT) { issue((kt + 1) & 1, kt + 1); cp_wait<1>(); }
        else             { cp_wait<0>(); }
        __syncthreads();
        const float* as = As[kt & 1];
        const float* bs = Bs[kt & 1];
        #pragma unroll
        for (int ko = 0; ko < 16; ko += 8) {
            uint32_t Bhi[4][2], Blo[4][2];
            #pragma unroll
            for (int j = 0; j < 4; j++) {
                const int nc = wn + 8*j + gid;
                split_tf32(bs[(ko + tig    )*BSTR + nc], Bhi[j][0], Blo[j][0]);
                split_tf32(bs[(ko + tig + 4)*BSTR + nc], Bhi[j][1], Blo[j][1]);
            }
            #pragma unroll
            for (int i = 0; i < 4; i++) {
                const int r0 = wm + 16*i + gid;
                uint32_t Ahi[4], Alo[4];
                split_tf32(as[ r0     *ASTR + ko + tig    ], Ahi[0], Alo[0]);
                split_tf32(as[(r0 + 8)*ASTR + ko + tig    ], Ahi[1], Alo[1]);
                split_tf32(as[ r0     *ASTR + ko + tig + 4], Ahi[2], Alo[2]);
                split_tf32(as[(r0 + 8)*ASTR + ko + tig + 4], Ahi[3], Alo[3]);
                #pragma unroll
                for (int j = 0; j < 4; j++) {
                    mma_tf32(acc[i][j], Alo, Bhi[j]);
                    mma_tf32(acc[i][j], Ahi, Blo[j]);
                    mma_tf32(acc[i][j], Ahi, Bhi[j]);
                }
            }
        }
        __syncthreads();
    }

    #pragma unroll
    for (int i = 0; i < 4; i++) {
        const int ma = m0 + wm + 16*i + gid;
        const int mb = ma + 8;
        #pragma unroll
        for (int j = 0; j < 4; j++) {
            const int nb = n0 + wn + 8*j + 2*tig;
            const float2 bv = *(const float2*)&bias[nb];
            float2 va = make_float2(acc[i][j].x + bv.x, acc[i][j].y + bv.y);
            float2 vb = make_float2(acc[i][j].z + bv.x, acc[i][j].w + bv.y);
            if (SCATTER) {
                const int which = nb / Ed;
                const int hh    = (nb % Ed) >> 6;
                const int d0    = nb & 63;
                float* dst = (which == 0) ? g_Q : (which == 1) ? g_K : g_V;
                {
                    int bb = ma >> 10, ss = ma & 1023;
                    *(float2*)&dst[(size_t)((bb*Hh + hh)*Sq + ss)*Dd + d0] = va;
                }
                {
                    int bb = mb >> 10, ss = mb & 1023;
                    *(float2*)&dst[(size_t)((bb*Hh + hh)*Sq + ss)*Dd + d0] = vb;
                }
            } else {
                *(float2*)&out[(size_t)ma * NDIM + nb] = va;
                *(float2*)&out[(size_t)mb * NDIM + nb] = vb;
            }
        }
    }
}

// ============================================================
// Fused attention v2: 3xTF32 scores (q pre-split, 4 acc chains),
// exact top-k, 1xTF32 PV (4 acc chains). 256 thr, 2 CTAs/SM.
// ============================================================
__global__ __launch_bounds__(256, 2) void attn_kernel() {
    extern __shared__ float sm[];
    float* q_hi = sm;                   // 16*68  = 1088
    float* q_lo = sm + 1088;            // 1088
    float* sc   = sm + 2176;            // 16*1028 = 16448
    float* kv   = sc + 16448;           // 128*68 = 8704
    float* invs = kv + 8704;            // 16
    // total 27344 floats = 109376 B

    const int t    = threadIdx.x;
    const int warp = t >> 5, lane = t & 31;
    const int gid  = lane >> 2, tig = lane & 3;
    const int bh = blockIdx.y;
    const int q0 = blockIdx.x * QT;
    const float* Qg = g_Q + (size_t)bh*Sq*Dd;
    const float* Kg = g_K + (size_t)bh*Sq*Dd;
    const float* Vg = g_V + (size_t)bh*Sq*Dd;

    const int prow = t >> 4, pc4 = (t & 15) << 2;
    float4 pf[8];
    auto ldg_tile = [&](const float* src, int kt0) {
        #pragma unroll
        for (int i = 0; i < 8; i++)
            pf[i] = *(const float4*)&src[(size_t)(kt0*KTT + prow + 16*i)*Dd + pc4];
    };
    auto sts_tile = [&]() {
        #pragma unroll
        for (int i = 0; i < 8; i++)
            *(float4*)&kv[(prow + 16*i)*KVP + pc4] = pf[i];
    };
    auto cp_tile = [&](const float* src, int kt0) {
        #pragma unroll
        for (int i = 0; i < 8; i++)
            cp16(&kv[(prow + 16*i)*KVP + pc4], &src[(size_t)(kt0*KTT + prow + 16*i)*Dd + pc4]);
        cp_commit();
    };

    // stage q tile pre-scaled AND pre-split into hi/lo
    {
        float4 v = *(const float4*)&Qg[(size_t)(q0 + prow)*Dd + pc4];
        v.x *= 0.125f; v.y *= 0.125f; v.z *= 0.125f; v.w *= 0.125f;
        uint32_t h, l;
        split_tf32(v.x, h, l); q_hi[prow*QSP + pc4+0] = __uint_as_float(h); q_lo[prow*QSP + pc4+0] = __uint_as_float(l);
        split_tf32(v.y, h, l); q_hi[prow*QSP + pc4+1] = __uint_as_float(h); q_lo[prow*QSP + pc4+1] = __uint_as_float(l);
        split_tf32(v.z, h, l); q_hi[prow*QSP + pc4+2] = __uint_as_float(h); q_lo[prow*QSP + pc4+2] = __uint_as_float(l);
        split_tf32(v.w, h, l); q_hi[prow*QSP + pc4+3] = __uint_as_float(h); q_lo[prow*QSP + pc4+3] = __uint_as_float(l);
    }

    // ================= scores (3xTF32 tensor core) =================
    cp_tile(Kg, 0);
    ldg_tile(Kg, 1);
    cp_wait<0>(); __syncthreads();

    for (int it = 0; it < 8; it++) {
        // 4 independent chains: 2 key n8-tiles x 2 k-halves
        float4 c0a = make_float4(0.f,0.f,0.f,0.f), c0b = c0a, c1a = c0a, c1b = c0a;
        #pragma unroll
        for (int ks = 0; ks < 8; ks++) {
            uint32_t Ah[4], Al[4], Bh[2], Bl[2];
            Ah[0] = __float_as_uint(q_hi[ gid     *QSP + ks*8 + tig    ]);
            Ah[1] = __float_as_uint(q_hi[(gid + 8)*QSP + ks*8 + tig    ]);
            Ah[2] = __float_as_uint(q_hi[ gid     *QSP + ks*8 + tig + 4]);
            Ah[3] = __float_as_uint(q_hi[(gid + 8)*QSP + ks*8 + tig + 4]);
            Al[0] = __float_as_uint(q_lo[ gid     *QSP + ks*8 + tig    ]);
            Al[1] = __float_as_uint(q_lo[(gid + 8)*QSP + ks*8 + tig    ]);
            Al[2] = __float_as_uint(q_lo[ gid     *QSP + ks*8 + tig + 4]);
            Al[3] = __float_as_uint(q_lo[(gid + 8)*QSP + ks*8 + tig + 4]);
            float4& c0 = (ks < 4) ? c0a : c0b;
            float4& c1 = (ks < 4) ? c1a : c1b;
            split_tf32(kv[(warp*16     + gid)*KVP + ks*8 + tig    ], Bh[0], Bl[0]);
            split_tf32(kv[(warp*16     + gid)*KVP + ks*8 + tig + 4], Bh[1], Bl[1]);
            mma_tf32(c0, Al, Bh); mma_tf32(c0, Ah, Bl); mma_tf32(c0, Ah, Bh);
            split_tf32(kv[(warp*16 + 8 + gid)*KVP + ks*8 + tig    ], Bh[0], Bl[0]);
            split_tf32(kv[(warp*16 + 8 + gid)*KVP + ks*8 + tig + 4], Bh[1], Bl[1]);
            mma_tf32(c1, Al, Bh); mma_tf32(c1, Ah, Bl); mma_tf32(c1, Ah, Bh);
        }
        float4 c0 = make_float4(c0a.x+c0b.x, c0a.y+c0b.y, c0a.z+c0b.z, c0a.w+c0b.w);
        float4 c1 = make_float4(c1a.x+c1b.x, c1a.y+c1b.y, c1a.z+c1b.z, c1a.w+c1b.w);
        const int kb = it*KTT + warp*16 + 2*tig;
        *(float2*)&sc[ gid   *SCP + kb    ] = make_float2(c0.x, c0.y);
        *(float2*)&sc[(gid+8)*SCP + kb    ] = make_float2(c0.z, c0.w);
        *(float2*)&sc[ gid   *SCP + kb + 8] = make_float2(c1.x, c1.y);
        *(float2*)&sc[(gid+8)*SCP + kb + 8] = make_float2(c1.z, c1.w);
        __syncthreads();
        if (it < 7) {
            sts_tile();
            if (it < 6) ldg_tile(Kg, it+2);
            __syncthreads();
        }
    }
    __syncthreads();

    cp_tile(Vg, 0);   // V0 flies during top-k

    // ====== exact top-k threshold + softmax in place ======
    {
        const int lane5 = t & 31;
        for (int r = warp*2; r < warp*2 + 2; r++) {
            float* row = sc + r*SCP;
            unsigned u[32];
            float mx = -3.4e38f;
            #pragma unroll
            for (int i = 0; i < 32; i++) {
                float f = row[i*32 + lane5];
                mx = fmaxf(mx, f);
                unsigned b = __float_as_uint(f);
                u[i] = b ^ (unsigned)(((int)b >> 31) | (int)0x80000000);
            }
            #pragma unroll
            for (int o = 16; o; o >>= 1) mx = fmaxf(mx, __shfl_xor_sync(0xffffffffu, mx, o));

            unsigned pref = 0;
            #pragma unroll 1
            for (int bb = 31; bb >= 0; bb--) {
                unsigned trial = pref | (1u << bb);
                int c = 0;
                #pragma unroll
                for (int i = 0; i < 32; i++) c += (u[i] >= trial) ? 1 : 0;
                c = (int)__reduce_add_sync(0xffffffffu, (unsigned)c);
                if (c >= TOPK) pref = trial;
            }

            float ssum = 0.f;
            #pragma unroll
            for (int i = 0; i < 32; i++) {
                float p = 0.f;
                if (u[i] >= pref) {
                    unsigned b = (u[i] & 0x80000000u) ? (u[i] ^ 0x80000000u) : ~u[i];
                    p = __expf(__uint_as_float(b) - mx);
                }
                ssum += p;
                row[i*32 + lane5] = p;
            }
            #pragma unroll
            for (int o = 16; o; o >>= 1) ssum += __shfl_xor_sync(0xffffffffu, ssum, o);
            if (lane5 == 0) invs[r] = 1.f / ssum;
        }
    }

    ldg_tile(Vg, 1);
    cp_wait<0>(); __syncthreads();

    // ================= PV (1xTF32 tensor core, 4 chains) =================
    // warp owns d-cols [8*warp, 8*warp+8); acc[j] accumulates ks-chunk j
    float4 oc[4];
    #pragma unroll
    for (int j = 0; j < 4; j++) oc[j] = make_float4(0.f,0.f,0.f,0.f);

    for (int it = 0; it < 8; it++) {
        const int kb = it*KTT;
        #pragma unroll
        for (int ks = 0; ks < 16; ks++) {
            uint32_t Ah[4], Bh[2];
            Ah[0] = f2tf(sc[ gid   *SCP + kb + ks*8 + tig    ]);
            Ah[1] = f2tf(sc[(gid+8)*SCP + kb + ks*8 + tig    ]);
            Ah[2] = f2tf(sc[ gid   *SCP + kb + ks*8 + tig + 4]);
            Ah[3] = f2tf(sc[(gid+8)*SCP + kb + ks*8 + tig + 4]);
            Bh[0] = f2tf(kv[(ks*8 + tig    )*KVP + warp*8 + gid]);
            Bh[1] = f2tf(kv[(ks*8 + tig + 4)*KVP + warp*8 + gid]);
            mma_tf32(oc[ks >> 2], Ah, Bh);
        }
        __syncthreads();
        if (it < 7) {
            sts_tile();
            if (it < 6) ldg_tile(Vg, it+2);
            __syncthreads();
        }
    }

    // epilogue: combine chains, normalize, store
    {
        float4 o;
        o.x = (oc[0].x + oc[1].x) + (oc[2].x + oc[3].x);
        o.y = (oc[0].y + oc[1].y) + (oc[2].y + oc[3].y);
        o.z = (oc[0].z + oc[1].z) + (oc[2].z + oc[3].z);
        o.w = (oc[0].w + oc[1].w) + (oc[2].w + oc[3].w);
        const int bb = bh / Hh, hh = bh % Hh;
        const float iv0 = invs[gid], iv1 = invs[gid + 8];
        const int d0 = warp*8 + 2*tig;
        *(float2*)&g_AO[(size_t)((bb*Sq + q0 + gid    )*Hh + hh)*Dd + d0] = make_float2(o.x*iv0, o.y*iv0);
        *(float2*)&g_AO[(size_t)((bb*Sq + q0 + gid + 8)*Hh + hh)*Dd + d0] = make_float2(o.z*iv1, o.w*iv1);
    }
}

// ============================================================
// launch
// ============================================================
extern "C" void kernel_launch(void* const* d_in, const int* in_sizes, int n_in,
                              void* d_out, int out_size) {
    const float* hidden = (const float*)d_in[0];
    const float* Wqkv   = (const float*)d_in[1];
    const float* bqkv   = (const float*)d_in[2];
    const float* Wproj  = (const float*)d_in[3];
    const float* bproj  = (const float*)d_in[4];
    float* out = (float*)d_out;

    const int attn_smem = (2176 + 16448 + 8704 + 16) * (int)sizeof(float); // 109376
    cudaFuncSetAttribute(attn_kernel, cudaFuncAttributeMaxDynamicSharedMemorySize, attn_smem);

    gemm_tf32<N3, true ><<<dim3(N3/128, (Bz*Sq)/128), 256>>>(hidden, Wqkv, bqkv, nullptr);
    attn_kernel<<<dim3(Sq/QT, Bz*Hh), 256, attn_smem>>>();
    gemm_tf32<Ed, false><<<dim3(Ed/128, (Bz*Sq)/128), 256>>>(nullptr, Wproj, bproj, out);
}